// round 14
// baseline (speedup 1.0000x reference)
#include <cuda_runtime.h>
#include <math_constants.h>

#define H 1536
#define W 1536
#define HW (H*W)
#define TS 64            // output tile
#define RAD 5            // KS/2
#define TMPW 74          // TS + 2*RAD
#define TMPSTR 76        // padded row stride
#define DD 6             // max |offset|
#define AW 86            // TMPW + 2*DD (columns)
#define AWY 92           // A rows incl. rolling-cache overshoot pad
#define ASTR 88          // A plane row stride (floats)
#define APLANE (AWY*ASTR)
#define NTH 1024
#define SEGROWS 6
#define NSEG 13          // 12 full 6-row segs + 1 partial (rows 72..73)
#define BPLANE (TMPW*TMPSTR)        // 5624 floats
#define VSTR 76
#define SVPLANE (TS*VSTR)           // 4864 floats

// smem: sA planes[3*APLANE] | sTmp[4*BPLANE] | sV[2*SVPLANE]
#define SMEM_BYTES (3*APLANE*4 + 4*BPLANE*4 + 2*SVPLANE*4)  // 226048

__device__ float g_res[HW];

typedef unsigned long long ull;

__device__ __forceinline__ float sqrt_approx(float x) {
    float r;
    asm("sqrt.approx.f32 %0, %1;" : "=f"(r) : "f"(x));
    return r;
}
__device__ __forceinline__ ull add2(ull a, ull b) {
    ull r; asm("add.rn.f32x2 %0, %1, %2;" : "=l"(r) : "l"(a), "l"(b)); return r;
}

__global__ __launch_bounds__(NTH, 1)
void dewarp_main(const float* __restrict__ A, const float* __restrict__ B) {
    extern __shared__ unsigned char smem_raw[];
    float* sA0   = (float*)smem_raw;
    float* sA1   = sA0 + APLANE;
    float* sA2   = sA1 + APLANE;
    float* sTmpB = sA2 + APLANE;          // 4 buffers (2 pairs x 2 halves)
    float* sVB   = sTmpB + 4*BPLANE;      // 2 buffers

    const int tid = threadIdx.x;
    const int by0 = blockIdx.y * TS, bx0 = blockIdx.x * TS;

    // ---- Load zero-padded A region into 3 planes (incl. overshoot rows) ----
    for (int i = tid; i < AWY*AW; i += NTH) {
        int ay = i / AW, ax = i - ay*AW;
        int gy = by0 - (RAD+DD) + ay;
        int gx = bx0 - (RAD+DD) + ax;
        float v0 = 0.f, v1 = 0.f, v2 = 0.f;
        if ((unsigned)gy < (unsigned)H && (unsigned)gx < (unsigned)W) {
            int g = gy*W + gx;
            v0 = A[g]; v1 = A[g + HW]; v2 = A[g + 2*HW];
        }
        int s = ay*ASTR + ax;
        sA0[s] = v0; sA1[s] = v1; sA2[s] = v2;
    }

    // ---- Pre-zero all 4 tmp buffers (halo-invalid entries stay 0 forever) ----
    for (int i = tid; i < 4*BPLANE; i += NTH) sTmpB[i] = 0.f;

    // ---- P1 ownership: thread = (6-row segment, column) ----
    const int seg   = tid / TMPW;          // 0..13 (>=NSEG -> inactive)
    const int tx    = tid - seg*TMPW;      // 0..73
    const bool p1act = (seg < NSEG);
    const int ty0   = seg * SEGROWS;       // 0,6,...,72
    const int tb    = ty0*TMPSTR + tx;     // tmp write base
    const int axb   = tx + DD;             // A column base (add dxo)

    // ---- B into registers (negated), validity mask ----
    float nb0s[SEGROWS], nb1s[SEGROWS], nb2s[SEGROWS];
    unsigned vldmask = 0;
    #pragma unroll
    for (int r = 0; r < SEGROWS; r++) {
        int ty = ty0 + r;
        int gy = by0 - RAD + ty;
        int gx = bx0 - RAD + tx;
        bool inb = p1act && (ty < TMPW) &&
                   ((unsigned)gy < (unsigned)H) && ((unsigned)gx < (unsigned)W);
        float v0 = 0.f, v1 = 0.f, v2 = 0.f;
        if (inb) {
            int g = gy*W + gx;
            v0 = B[g]; v1 = B[g + HW]; v2 = B[g + 2*HW];
        }
        nb0s[r] = -v0; nb1s[r] = -v1; nb2s[r] = -v2;
        if (inb) vldmask |= (1u << r);
    }

    // ---- rolling A cache (18 regs), consistent iff P1 called for o=0,1,2,... ----
    float c0[SEGROWS], c1[SEGROWS], c2[SEGROWS];
    #pragma unroll
    for (int i = 0; i < SEGROWS; i++) { c0[i] = 0.f; c1[i] = 0.f; c2[i] = 0.f; }

    // phase-2a ownership: 592 threads = 2 halves x 37 column-pairs x 8-row segs
    const bool vact = (tid < 592);
    const int  voff = (tid >= 296) ? 1 : 0;
    const int  vt   = tid - 296*voff;
    const int  vy0  = (vt / 37) * 8;
    const int  vtx  = (vt % 37) * 2;

    // phase-2b ownership: 4 consecutive x in one output row
    const int yo = tid >> 4;
    const int xs = (tid & 15) << 2;

    float wm0 = CUDART_INF_F, wm1 = CUDART_INF_F, wm2 = CUDART_INF_F, wm3 = CUDART_INF_F;
    float r0 = 0.f, r1 = 0.f, r2 = 0.f, r3 = 0.f;

    // ---- phase-1: rolling-cache tmp computation (values identical to R10) ----
    auto phase1 = [&](int o, float* __restrict__ sTmp) {
        const int od  = o / 13;
        const int dxo = od - DD;           // dx outer (reference loop order)
        const int dyo = (o - od*13) - DD;  // dy inner
        if (p1act) {
            const int ax = axb + dxo;
            if (dyo == -DD) {
                // dx boundary: full window reload (rows ty0 .. ty0+5)
                #pragma unroll
                for (int i = 0; i < SEGROWS; i++) {
                    int ia = (ty0 + i)*ASTR + ax;
                    c0[i] = sA0[ia]; c1[i] = sA1[ia]; c2[i] = sA2[ia];
                }
            } else {
                // slide window down one row, load the new bottom row
                #pragma unroll
                for (int i = 0; i < SEGROWS-1; i++) {
                    c0[i] = c0[i+1]; c1[i] = c1[i+1]; c2[i] = c2[i+1];
                }
                int ia = (ty0 + SEGROWS-1 + DD + dyo)*ASTR + ax;
                c0[SEGROWS-1] = sA0[ia];
                c1[SEGROWS-1] = sA1[ia];
                c2[SEGROWS-1] = sA2[ia];
            }
            #pragma unroll
            for (int r = 0; r < SEGROWS; r++) {
                if (vldmask >> r & 1u) {
                    float d0 = __fadd_rn(c0[r], nb0s[r]);   // == a - b exactly
                    float d1 = __fadd_rn(c1[r], nb1s[r]);
                    float d2 = __fadd_rn(c2[r], nb2s[r]);
                    float q  = __fadd_rn(__fadd_rn(__fmul_rn(d0,d0), __fmul_rn(d1,d1)),
                                         __fmul_rn(d2,d2));
                    sTmp[tb + r*TMPSTR] = sqrt_approx(q);
                }
            }
        }
    };

    __syncthreads();

    // ---- prologue: phase 1 for pair 0 (offsets 0,1) into buffers 0,1 ----
    phase1(0, sTmpB);
    phase1(1, sTmpB + BPLANE);
    __syncthreads();

    for (int p = 0; p < 85; ++p) {
        const int  o0   = 2*p;
        const bool has1 = (o0 + 1) < 169;
        float* curT = sTmpB + ((p & 1) ? 2*BPLANE : 0);

        // ======== phase 2a: vertical 11-tap subtree folds, both halves ========
        if (vact && (voff == 0 || has1)) {
            const float* sTmp = curT + voff*BPLANE;
            float*       sV   = sVB  + voff*SVPLANE;
            const float* base = sTmp + vy0*TMPSTR + vtx;
            ull v[18];
            #pragma unroll
            for (int j = 0; j < 18; j++)
                v[j] = *(const ull*)(base + j*TMPSTR);

            ull core = add2(add2(v[7], v[8]), add2(v[9], v[10]));
            ull a6 = v[6];
            ull a5 = add2(v[5], a6);
            ull a4 = add2(v[4], a5);
            ull a3 = add2(v[3], a4);
            ull a2 = add2(v[2], a3);
            ull a1 = add2(v[1], a2);
            ull a0 = add2(v[0], a1);
            ull b11 = v[11];
            ull b12 = add2(b11, v[12]);
            ull b13 = add2(b12, v[13]);
            ull b14 = add2(b13, v[14]);
            ull b15 = add2(b14, v[15]);
            ull b16 = add2(b15, v[16]);
            ull b17 = add2(b16, v[17]);

            float* vo = sV + vy0*VSTR + vtx;
            *(ull*)(vo + 0*VSTR) = add2(a0, core);
            *(ull*)(vo + 1*VSTR) = add2(add2(a1, core), b11);
            *(ull*)(vo + 2*VSTR) = add2(add2(a2, core), b12);
            *(ull*)(vo + 3*VSTR) = add2(add2(a3, core), b13);
            *(ull*)(vo + 4*VSTR) = add2(add2(a4, core), b14);
            *(ull*)(vo + 5*VSTR) = add2(add2(a5, core), b15);
            *(ull*)(vo + 6*VSTR) = add2(add2(a6, core), b16);
            *(ull*)(vo + 7*VSTR) = add2(core, b17);
        }
        __syncthreads();

        // ======== combined phase: P1(pair p+1) overlapped with P2b(pair p) ====
        if (p + 1 < 85) {
            float* nxtT = sTmpB + (((p + 1) & 1) ? 2*BPLANE : 0);
            phase1(2*(p+1), nxtT);
            if (2*(p+1) + 1 < 169) phase1(2*(p+1) + 1, nxtT + BPLANE);
        }

        #pragma unroll
        for (int half = 0; half < 2; half++) {
            if (half == 1 && !has1) break;
            const float* sTmp = curT + half*BPLANE;
            const float* sV   = sVB  + half*SVPLANE;

            const float* rowp = sV + yo*VSTR + xs;
            float4 q0 = *(const float4*)rowp;
            float4 q1 = *(const float4*)(rowp + 4);
            float4 q2 = *(const float4*)(rowp + 8);
            float2 q3 = *(const float2*)(rowp + 12);
            float v0 = q0.x, v1 = q0.y, v2  = q0.z, v3  = q0.w;
            float v4 = q1.x, v5 = q1.y, v6  = q1.z, v7  = q1.w;
            float v8 = q2.x, v9 = q2.y, v10 = q2.z, v11 = q2.w;
            float v12 = q3.x, v13 = q3.y;

            float core = __fadd_rn(
                __fadd_rn(__fadd_rn(v3, v4), __fadd_rn(v5, v6)),
                __fadd_rn(__fadd_rn(v7, v8), __fadd_rn(v9, v10)));
            float a2 = v2;
            float a1 = __fadd_rn(v1, a2);
            float a0 = __fadd_rn(v0, a1);
            float c11 = v11;
            float c12 = __fadd_rn(c11, v12);
            float c13 = __fadd_rn(c12, v13);

            float s0 = __fadd_rn(a0, core);
            float s1 = __fadd_rn(__fadd_rn(a1, core), c11);
            float s2 = __fadd_rn(__fadd_rn(a2, core), c12);
            float s3 = __fadd_rn(core, c13);

            const int cb = (yo + RAD)*TMPSTR + (xs + RAD);
            float t0 = sTmp[cb + 0];
            float t1 = sTmp[cb + 1];
            float t2 = sTmp[cb + 2];
            float t3 = sTmp[cb + 3];

            // argmin over s (== argmin over w = s/121); ties -> newer candidate
            if (s0 <= wm0) { wm0 = s0; r0 = t0; }
            if (s1 <= wm1) { wm1 = s1; r1 = t1; }
            if (s2 <= wm2) { wm2 = s2; r2 = t2; }
            if (s3 <= wm3) { wm3 = s3; r3 = t3; }
        }
        __syncthreads();   // orders P2b reads & next P1 writes before P2a(p+1)
    }

    float4 out4 = make_float4(r0, r1, r2, r3);
    *(float4*)(g_res + (by0 + yo)*W + (bx0 + xs)) = out4;
}

// ---- final 3x3 min-pool (inf pad == clamped window) ----
__global__ void minpool3(float* __restrict__ out) {
    int x = blockIdx.x*blockDim.x + threadIdx.x;
    int y = blockIdx.y*blockDim.y + threadIdx.y;
    if (x >= W || y >= H) return;
    float m = CUDART_INF_F;
    #pragma unroll
    for (int dy = -1; dy <= 1; dy++) {
        int yy = y + dy;
        if ((unsigned)yy >= (unsigned)H) continue;
        const float* row = g_res + yy*W;
        #pragma unroll
        for (int dx = -1; dx <= 1; dx++) {
            int xx = x + dx;
            if ((unsigned)xx < (unsigned)W) m = fminf(m, row[xx]);
        }
    }
    out[y*W + x] = m;
}

extern "C" void kernel_launch(void* const* d_in, const int* in_sizes, int n_in,
                              void* d_out, int out_size) {
    const float* A = (const float*)d_in[0];
    const float* B = (const float*)d_in[1];
    float* out = (float*)d_out;

    cudaFuncSetAttribute(dewarp_main,
                         cudaFuncAttributeMaxDynamicSharedMemorySize, SMEM_BYTES);

    dim3 grid(W/TS, H/TS);
    dewarp_main<<<grid, NTH, SMEM_BYTES>>>(A, B);

    dim3 b2(32, 8);
    dim3 g2(W/32, H/8);
    minpool3<<<g2, b2>>>(out);
}

// round 15
// speedup vs baseline: 1.4517x; 1.4517x over previous
#include <cuda_runtime.h>
#include <math_constants.h>

#define H 1536
#define W 1536
#define HW (H*W)
#define TS 64            // output tile
#define RAD 5            // KS/2
#define TMPW 74          // TS + 2*RAD
#define TMPSTR 76        // padded row stride
#define DD 6             // max |offset|
#define AW 86            // TMPW + 2*DD (columns)
#define AWY 90           // A rows (max accessed row = 89)
#define ASTR 88          // A plane row stride (floats)
#define APLANE (AWY*ASTR)           // 7920
#define NTH 1024
#define SEGROWS 6
#define NSEG 13                      // 13 segs x 6 rows = 78 >= 74
#define BPLANE (TMPW*TMPSTR)        // 5624 floats
#define VSTR 76
#define SVPLANE (TS*VSTR)           // 4864 floats

// smem: sA planes[3*APLANE] | sTmp[4*BPLANE] | sV[2*SVPLANE]
#define SMEM_BYTES (3*APLANE*4 + 4*BPLANE*4 + 2*SVPLANE*4)  // 223936

__device__ float g_res[HW];

typedef unsigned long long ull;

__device__ __forceinline__ float sqrt_approx(float x) {
    float r;
    asm("sqrt.approx.f32 %0, %1;" : "=f"(r) : "f"(x));
    return r;
}
__device__ __forceinline__ ull add2(ull a, ull b) {
    ull r; asm("add.rn.f32x2 %0, %1, %2;" : "=l"(r) : "l"(a), "l"(b)); return r;
}

__global__ __launch_bounds__(NTH, 1)
void dewarp_main(const float* __restrict__ A, const float* __restrict__ B) {
    extern __shared__ unsigned char smem_raw[];
    float* sA0   = (float*)smem_raw;
    float* sA1   = sA0 + APLANE;
    float* sA2   = sA1 + APLANE;
    float* sTmpB = sA2 + APLANE;          // 4 buffers (2 pairs x 2 halves)
    float* sVB   = sTmpB + 4*BPLANE;      // 2 buffers

    const int tid = threadIdx.x;
    const int by0 = blockIdx.y * TS, bx0 = blockIdx.x * TS;

    // ---- Load zero-padded A region into 3 planes ----
    for (int i = tid; i < AWY*AW; i += NTH) {
        int ay = i / AW, ax = i - ay*AW;
        int gy = by0 - (RAD+DD) + ay;
        int gx = bx0 - (RAD+DD) + ax;
        float v0 = 0.f, v1 = 0.f, v2 = 0.f;
        if ((unsigned)gy < (unsigned)H && (unsigned)gx < (unsigned)W) {
            int g = gy*W + gx;
            v0 = A[g]; v1 = A[g + HW]; v2 = A[g + 2*HW];
        }
        int s = ay*ASTR + ax;
        sA0[s] = v0; sA1[s] = v1; sA2[s] = v2;
    }

    // ---- Pre-zero all 4 tmp buffers (halo-invalid entries stay 0 forever) ----
    for (int i = tid; i < 4*BPLANE; i += NTH) sTmpB[i] = 0.f;

    // ---- P1 ownership: thread = (6-row segment, column) ----
    const int  seg   = tid / TMPW;          // 0..13 (>=NSEG -> inactive)
    const int  tx    = tid - seg*TMPW;      // 0..73
    const bool p1act = (seg < NSEG);
    const int  ty0   = seg * SEGROWS;       // 0,6,...,72
    const int  tb    = ty0*TMPSTR + tx;     // tmp write base

    // ---- B into registers (negated), validity mask ----
    float nb0s[SEGROWS], nb1s[SEGROWS], nb2s[SEGROWS];
    unsigned vldmask = 0;
    #pragma unroll
    for (int r = 0; r < SEGROWS; r++) {
        int ty = ty0 + r;
        int gy = by0 - RAD + ty;
        int gx = bx0 - RAD + tx;
        bool inb = p1act && (ty < TMPW) &&
                   ((unsigned)gy < (unsigned)H) && ((unsigned)gx < (unsigned)W);
        float v0 = 0.f, v1 = 0.f, v2 = 0.f;
        if (inb) {
            int g = gy*W + gx;
            v0 = B[g]; v1 = B[g + HW]; v2 = B[g + 2*HW];
        }
        nb0s[r] = -v0; nb1s[r] = -v1; nb2s[r] = -v2;
        if (inb) vldmask |= (1u << r);
    }

    // phase-2a ownership: 592 threads = 2 halves x 37 column-pairs x 8-row segs
    const bool vact = (tid < 592);
    const int  voff = (tid >= 296) ? 1 : 0;
    const int  vt   = tid - 296*voff;
    const int  vy0  = (vt / 37) * 8;
    const int  vtx  = (vt % 37) * 2;

    // phase-2b ownership: 4 consecutive x in one output row
    const int yo = tid >> 4;
    const int xs = (tid & 15) << 2;

    float wm0 = CUDART_INF_F, wm1 = CUDART_INF_F, wm2 = CUDART_INF_F, wm3 = CUDART_INF_F;
    float r0 = 0.f, r1 = 0.f, r2 = 0.f, r3 = 0.f;

    // ---- single-offset phase 1 (fallback path) ----
    auto p1_single = [&](int o, float* __restrict__ sTmp) {
        if (!p1act) return;
        const int od  = o / 13;
        const int dxo = od - DD;
        const int dyo = (o - od*13) - DD;
        const int rb  = (ty0 + DD + dyo)*ASTR + (tx + DD + dxo);
        #pragma unroll
        for (int r = 0; r < SEGROWS; r++) {
            if (vldmask >> r & 1u) {
                int ia = rb + r*ASTR;
                float d0 = __fadd_rn(sA0[ia], nb0s[r]);
                float d1 = __fadd_rn(sA1[ia], nb1s[r]);
                float d2 = __fadd_rn(sA2[ia], nb2s[r]);
                float q  = __fadd_rn(__fadd_rn(__fmul_rn(d0,d0), __fmul_rn(d1,d1)),
                                     __fmul_rn(d2,d2));
                sTmp[tb + r*TMPSTR] = sqrt_approx(q);
            }
        }
    };

    // ---- fused pair: offsets (o0, o0+1), same dx, dy differs by 1 ----
    auto p1_pair = [&](int o0, float* __restrict__ bA, float* __restrict__ bB) {
        if (!p1act) return;
        const int od  = o0 / 13;
        const int dxo = od - DD;
        const int dyo = (o0 - od*13) - DD;
        const int rb  = (ty0 + DD + dyo)*ASTR + (tx + DD + dxo);
        float p0 = sA0[rb], p1v = sA1[rb], p2 = sA2[rb];
        #pragma unroll
        for (int r = 0; r < SEGROWS; r++) {
            int ia = rb + (r+1)*ASTR;
            float n0 = sA0[ia], n1 = sA1[ia], n2 = sA2[ia];
            if (vldmask >> r & 1u) {
                // offset o0: row r
                float d0 = __fadd_rn(p0,  nb0s[r]);
                float d1 = __fadd_rn(p1v, nb1s[r]);
                float d2 = __fadd_rn(p2,  nb2s[r]);
                float qa = __fadd_rn(__fadd_rn(__fmul_rn(d0,d0), __fmul_rn(d1,d1)),
                                     __fmul_rn(d2,d2));
                bA[tb + r*TMPSTR] = sqrt_approx(qa);
                // offset o0+1: row r+1 (same B)
                float e0 = __fadd_rn(n0, nb0s[r]);
                float e1 = __fadd_rn(n1, nb1s[r]);
                float e2 = __fadd_rn(n2, nb2s[r]);
                float qb = __fadd_rn(__fadd_rn(__fmul_rn(e0,e0), __fmul_rn(e1,e1)),
                                     __fmul_rn(e2,e2));
                bB[tb + r*TMPSTR] = sqrt_approx(qb);
            }
            p0 = n0; p1v = n1; p2 = n2;
        }
    };

    // ---- dispatcher: fused if pair shares dx, else two singles ----
    auto phase1x2 = [&](int o0, float* __restrict__ bA, float* __restrict__ bB) {
        const bool has1 = (o0 + 1) < 169;
        if (has1 && (o0 % 13) != 12) {
            p1_pair(o0, bA, bB);
        } else {
            p1_single(o0, bA);
            if (has1) p1_single(o0 + 1, bB);
        }
    };

    __syncthreads();

    // ---- prologue: phase 1 for pair 0 (offsets 0,1) into buffers 0,1 ----
    phase1x2(0, sTmpB, sTmpB + BPLANE);
    __syncthreads();

    for (int p = 0; p < 85; ++p) {
        const int  o0   = 2*p;
        const bool has1 = (o0 + 1) < 169;
        float* curT = sTmpB + ((p & 1) ? 2*BPLANE : 0);

        // ======== phase 2a: vertical 11-tap subtree folds, both halves ========
        if (vact && (voff == 0 || has1)) {
            const float* sTmp = curT + voff*BPLANE;
            float*       sV   = sVB  + voff*SVPLANE;
            const float* base = sTmp + vy0*TMPSTR + vtx;
            ull v[18];
            #pragma unroll
            for (int j = 0; j < 18; j++)
                v[j] = *(const ull*)(base + j*TMPSTR);

            ull core = add2(add2(v[7], v[8]), add2(v[9], v[10]));
            ull a6 = v[6];
            ull a5 = add2(v[5], a6);
            ull a4 = add2(v[4], a5);
            ull a3 = add2(v[3], a4);
            ull a2 = add2(v[2], a3);
            ull a1 = add2(v[1], a2);
            ull a0 = add2(v[0], a1);
            ull b11 = v[11];
            ull b12 = add2(b11, v[12]);
            ull b13 = add2(b12, v[13]);
            ull b14 = add2(b13, v[14]);
            ull b15 = add2(b14, v[15]);
            ull b16 = add2(b15, v[16]);
            ull b17 = add2(b16, v[17]);

            float* vo = sV + vy0*VSTR + vtx;
            *(ull*)(vo + 0*VSTR) = add2(a0, core);
            *(ull*)(vo + 1*VSTR) = add2(add2(a1, core), b11);
            *(ull*)(vo + 2*VSTR) = add2(add2(a2, core), b12);
            *(ull*)(vo + 3*VSTR) = add2(add2(a3, core), b13);
            *(ull*)(vo + 4*VSTR) = add2(add2(a4, core), b14);
            *(ull*)(vo + 5*VSTR) = add2(add2(a5, core), b15);
            *(ull*)(vo + 6*VSTR) = add2(add2(a6, core), b16);
            *(ull*)(vo + 7*VSTR) = add2(core, b17);
        }
        __syncthreads();

        // ======== combined phase: P1(pair p+1) overlapped with P2b(pair p) ====
        if (p + 1 < 85) {
            float* nxtT = sTmpB + (((p + 1) & 1) ? 2*BPLANE : 0);
            phase1x2(2*(p+1), nxtT, nxtT + BPLANE);
        }

        #pragma unroll
        for (int half = 0; half < 2; half++) {
            if (half == 1 && !has1) break;
            const float* sTmp = curT + half*BPLANE;
            const float* sV   = sVB  + half*SVPLANE;

            const float* rowp = sV + yo*VSTR + xs;
            float4 q0 = *(const float4*)rowp;
            float4 q1 = *(const float4*)(rowp + 4);
            float4 q2 = *(const float4*)(rowp + 8);
            float2 q3 = *(const float2*)(rowp + 12);
            float v0 = q0.x, v1 = q0.y, v2  = q0.z, v3  = q0.w;
            float v4 = q1.x, v5 = q1.y, v6  = q1.z, v7  = q1.w;
            float v8 = q2.x, v9 = q2.y, v10 = q2.z, v11 = q2.w;
            float v12 = q3.x, v13 = q3.y;

            float core = __fadd_rn(
                __fadd_rn(__fadd_rn(v3, v4), __fadd_rn(v5, v6)),
                __fadd_rn(__fadd_rn(v7, v8), __fadd_rn(v9, v10)));
            float a2 = v2;
            float a1 = __fadd_rn(v1, a2);
            float a0 = __fadd_rn(v0, a1);
            float c11 = v11;
            float c12 = __fadd_rn(c11, v12);
            float c13 = __fadd_rn(c12, v13);

            float s0 = __fadd_rn(a0, core);
            float s1 = __fadd_rn(__fadd_rn(a1, core), c11);
            float s2 = __fadd_rn(__fadd_rn(a2, core), c12);
            float s3 = __fadd_rn(core, c13);

            const int cb = (yo + RAD)*TMPSTR + (xs + RAD);
            float t0 = sTmp[cb + 0];
            float t1 = sTmp[cb + 1];
            float t2 = sTmp[cb + 2];
            float t3 = sTmp[cb + 3];

            // argmin over s (== argmin over w = s/121); ties -> newer candidate
            if (s0 <= wm0) { wm0 = s0; r0 = t0; }
            if (s1 <= wm1) { wm1 = s1; r1 = t1; }
            if (s2 <= wm2) { wm2 = s2; r2 = t2; }
            if (s3 <= wm3) { wm3 = s3; r3 = t3; }
        }
        __syncthreads();   // orders P2b reads & next P1 writes before P2a(p+1)
    }

    float4 out4 = make_float4(r0, r1, r2, r3);
    *(float4*)(g_res + (by0 + yo)*W + (bx0 + xs)) = out4;
}

// ---- final 3x3 min-pool (inf pad == clamped window) ----
__global__ void minpool3(float* __restrict__ out) {
    int x = blockIdx.x*blockDim.x + threadIdx.x;
    int y = blockIdx.y*blockDim.y + threadIdx.y;
    if (x >= W || y >= H) return;
    float m = CUDART_INF_F;
    #pragma unroll
    for (int dy = -1; dy <= 1; dy++) {
        int yy = y + dy;
        if ((unsigned)yy >= (unsigned)H) continue;
        const float* row = g_res + yy*W;
        #pragma unroll
        for (int dx = -1; dx <= 1; dx++) {
            int xx = x + dx;
            if ((unsigned)xx < (unsigned)W) m = fminf(m, row[xx]);
        }
    }
    out[y*W + x] = m;
}

extern "C" void kernel_launch(void* const* d_in, const int* in_sizes, int n_in,
                              void* d_out, int out_size) {
    const float* A = (const float*)d_in[0];
    const float* B = (const float*)d_in[1];
    float* out = (float*)d_out;

    cudaFuncSetAttribute(dewarp_main,
                         cudaFuncAttributeMaxDynamicSharedMemorySize, SMEM_BYTES);

    dim3 grid(W/TS, H/TS);
    dewarp_main<<<grid, NTH, SMEM_BYTES>>>(A, B);

    dim3 b2(32, 8);
    dim3 g2(W/32, H/8);
    minpool3<<<g2, b2>>>(out);
}

// round 16
// speedup vs baseline: 1.4858x; 1.0235x over previous
#include <cuda_runtime.h>
#include <math_constants.h>

#define H 1536
#define W 1536
#define HW (H*W)
#define TS 64            // output tile
#define RAD 5            // KS/2
#define TMPW 74          // TS + 2*RAD
#define TMPSTR 76        // padded row stride
#define DD 6             // max |offset|
#define AW 86            // TMPW + 2*DD (columns)
#define AWY 90           // A rows (max accessed row = 89)
#define ASTR 88          // A plane row stride (floats)
#define APLANE (AWY*ASTR)           // 7920
#define NTH 1024
#define SEGROWS 6
#define NSEG 13                      // 13 segs x 6 rows = 78 >= 74
#define BPLANE (TMPW*TMPSTR)        // 5624 floats
#define VSTR 76
#define SVPLANE (TS*VSTR)           // 4864 floats

// smem: sA planes[3*APLANE] | sTmp[4*BPLANE] | sV[2*SVPLANE]
#define SMEM_BYTES (3*APLANE*4 + 4*BPLANE*4 + 2*SVPLANE*4)  // 223936

__device__ float g_res[HW];

typedef unsigned long long ull;

__device__ __forceinline__ float sqrt_approx(float x) {
    float r;
    asm("sqrt.approx.f32 %0, %1;" : "=f"(r) : "f"(x));
    return r;
}
__device__ __forceinline__ ull pk2(float lo, float hi) {
    ull r; asm("mov.b64 %0, {%1, %2};" : "=l"(r) : "f"(lo), "f"(hi)); return r;
}
__device__ __forceinline__ void upk2(ull v, float& lo, float& hi) {
    asm("mov.b64 {%0, %1}, %2;" : "=f"(lo), "=f"(hi) : "l"(v));
}
__device__ __forceinline__ ull add2(ull a, ull b) {
    ull r; asm("add.rn.f32x2 %0, %1, %2;" : "=l"(r) : "l"(a), "l"(b)); return r;
}
__device__ __forceinline__ ull mul2(ull a, ull b) {
    ull r; asm("mul.rn.f32x2 %0, %1, %2;" : "=l"(r) : "l"(a), "l"(b)); return r;
}

__global__ __launch_bounds__(NTH, 1)
void dewarp_main(const float* __restrict__ A, const float* __restrict__ B) {
    extern __shared__ unsigned char smem_raw[];
    float* sA0   = (float*)smem_raw;
    float* sA1   = sA0 + APLANE;
    float* sA2   = sA1 + APLANE;
    float* sTmpB = sA2 + APLANE;          // 4 buffers (2 pairs x 2 halves)
    float* sVB   = sTmpB + 4*BPLANE;      // 2 buffers

    const int tid = threadIdx.x;
    const int by0 = blockIdx.y * TS, bx0 = blockIdx.x * TS;

    // ---- Load zero-padded A region into 3 planes ----
    for (int i = tid; i < AWY*AW; i += NTH) {
        int ay = i / AW, ax = i - ay*AW;
        int gy = by0 - (RAD+DD) + ay;
        int gx = bx0 - (RAD+DD) + ax;
        float v0 = 0.f, v1 = 0.f, v2 = 0.f;
        if ((unsigned)gy < (unsigned)H && (unsigned)gx < (unsigned)W) {
            int g = gy*W + gx;
            v0 = A[g]; v1 = A[g + HW]; v2 = A[g + 2*HW];
        }
        int s = ay*ASTR + ax;
        sA0[s] = v0; sA1[s] = v1; sA2[s] = v2;
    }

    // ---- Pre-zero all 4 tmp buffers (halo-invalid entries stay 0 forever) ----
    for (int i = tid; i < 4*BPLANE; i += NTH) sTmpB[i] = 0.f;

    // ---- P1 ownership: thread = (6-row segment, column) ----
    const int  seg   = tid / TMPW;          // 0..13 (>=NSEG -> inactive)
    const int  tx    = tid - seg*TMPW;      // 0..73
    const bool p1act = (seg < NSEG);
    const int  ty0   = seg * SEGROWS;       // 0,6,...,72
    const int  tb    = ty0*TMPSTR + tx;     // tmp write base

    // ---- B into registers (negated), validity mask ----
    float nb0s[SEGROWS], nb1s[SEGROWS], nb2s[SEGROWS];
    unsigned vldmask = 0;
    #pragma unroll
    for (int r = 0; r < SEGROWS; r++) {
        int ty = ty0 + r;
        int gy = by0 - RAD + ty;
        int gx = bx0 - RAD + tx;
        bool inb = p1act && (ty < TMPW) &&
                   ((unsigned)gy < (unsigned)H) && ((unsigned)gx < (unsigned)W);
        float v0 = 0.f, v1 = 0.f, v2 = 0.f;
        if (inb) {
            int g = gy*W + gx;
            v0 = B[g]; v1 = B[g + HW]; v2 = B[g + 2*HW];
        }
        nb0s[r] = -v0; nb1s[r] = -v1; nb2s[r] = -v2;
        if (inb) vldmask |= (1u << r);
    }

    // phase-2a ownership: 592 threads = 2 halves x 37 column-pairs x 8-row segs
    const bool vact = (tid < 592);
    const int  voff = (tid >= 296) ? 1 : 0;
    const int  vt   = tid - 296*voff;
    const int  vy0  = (vt / 37) * 8;
    const int  vtx  = (vt % 37) * 2;

    // phase-2b ownership: 4 consecutive x in one output row
    const int yo = tid >> 4;
    const int xs = (tid & 15) << 2;

    float wm0 = CUDART_INF_F, wm1 = CUDART_INF_F, wm2 = CUDART_INF_F, wm3 = CUDART_INF_F;
    float r0 = 0.f, r1 = 0.f, r2 = 0.f, r3 = 0.f;

    // ---- single-offset phase 1 (fallback path, scalar — bit-equal) ----
    auto p1_single = [&](int o, float* __restrict__ sTmp) {
        if (!p1act) return;
        const int od  = o / 13;
        const int dxo = od - DD;
        const int dyo = (o - od*13) - DD;
        const int rb  = (ty0 + DD + dyo)*ASTR + (tx + DD + dxo);
        #pragma unroll
        for (int r = 0; r < SEGROWS; r++) {
            if (vldmask >> r & 1u) {
                int ia = rb + r*ASTR;
                float d0 = __fadd_rn(sA0[ia], nb0s[r]);
                float d1 = __fadd_rn(sA1[ia], nb1s[r]);
                float d2 = __fadd_rn(sA2[ia], nb2s[r]);
                float q  = __fadd_rn(__fadd_rn(__fmul_rn(d0,d0), __fmul_rn(d1,d1)),
                                     __fmul_rn(d2,d2));
                sTmp[tb + r*TMPSTR] = sqrt_approx(q);
            }
        }
    };

    // ---- fused pair, f32x2-packed across the two offsets (lanes exact rn) ----
    auto p1_pair = [&](int o0, float* __restrict__ bA, float* __restrict__ bB) {
        if (!p1act) return;
        const int od  = o0 / 13;
        const int dxo = od - DD;
        const int dyo = (o0 - od*13) - DD;
        const int rb  = (ty0 + DD + dyo)*ASTR + (tx + DD + dxo);
        float p0 = sA0[rb], p1v = sA1[rb], p2 = sA2[rb];
        #pragma unroll
        for (int r = 0; r < SEGROWS; r++) {
            int ia = rb + (r+1)*ASTR;
            float n0 = sA0[ia], n1 = sA1[ia], n2 = sA2[ia];
            if (vldmask >> r & 1u) {
                // lane0: offset o0 (row r);  lane1: offset o0+1 (row r+1)
                ull a0p = pk2(p0,  n0);
                ull a1p = pk2(p1v, n1);
                ull a2p = pk2(p2,  n2);
                ull b0p = pk2(nb0s[r], nb0s[r]);
                ull b1p = pk2(nb1s[r], nb1s[r]);
                ull b2p = pk2(nb2s[r], nb2s[r]);
                ull d0 = add2(a0p, b0p);   // == a - b per lane, exactly
                ull d1 = add2(a1p, b1p);
                ull d2 = add2(a2p, b2p);
                ull q  = add2(add2(mul2(d0,d0), mul2(d1,d1)), mul2(d2,d2));
                float qa, qb; upk2(q, qa, qb);
                bA[tb + r*TMPSTR] = sqrt_approx(qa);
                bB[tb + r*TMPSTR] = sqrt_approx(qb);
            }
            p0 = n0; p1v = n1; p2 = n2;
        }
    };

    // ---- dispatcher: fused if pair shares dx, else two singles ----
    auto phase1x2 = [&](int o0, float* __restrict__ bA, float* __restrict__ bB) {
        const bool has1 = (o0 + 1) < 169;
        if (has1 && (o0 % 13) != 12) {
            p1_pair(o0, bA, bB);
        } else {
            p1_single(o0, bA);
            if (has1) p1_single(o0 + 1, bB);
        }
    };

    __syncthreads();

    // ---- prologue: phase 1 for pair 0 (offsets 0,1) into buffers 0,1 ----
    phase1x2(0, sTmpB, sTmpB + BPLANE);
    __syncthreads();

    for (int p = 0; p < 85; ++p) {
        const int  o0   = 2*p;
        const bool has1 = (o0 + 1) < 169;
        float* curT = sTmpB + ((p & 1) ? 2*BPLANE : 0);

        // ======== phase 2a: vertical 11-tap subtree folds, both halves ========
        if (vact && (voff == 0 || has1)) {
            const float* sTmp = curT + voff*BPLANE;
            float*       sV   = sVB  + voff*SVPLANE;
            const float* base = sTmp + vy0*TMPSTR + vtx;
            ull v[18];
            #pragma unroll
            for (int j = 0; j < 18; j++)
                v[j] = *(const ull*)(base + j*TMPSTR);

            ull core = add2(add2(v[7], v[8]), add2(v[9], v[10]));
            ull a6 = v[6];
            ull a5 = add2(v[5], a6);
            ull a4 = add2(v[4], a5);
            ull a3 = add2(v[3], a4);
            ull a2 = add2(v[2], a3);
            ull a1 = add2(v[1], a2);
            ull a0 = add2(v[0], a1);
            ull b11 = v[11];
            ull b12 = add2(b11, v[12]);
            ull b13 = add2(b12, v[13]);
            ull b14 = add2(b13, v[14]);
            ull b15 = add2(b14, v[15]);
            ull b16 = add2(b15, v[16]);
            ull b17 = add2(b16, v[17]);

            float* vo = sV + vy0*VSTR + vtx;
            *(ull*)(vo + 0*VSTR) = add2(a0, core);
            *(ull*)(vo + 1*VSTR) = add2(add2(a1, core), b11);
            *(ull*)(vo + 2*VSTR) = add2(add2(a2, core), b12);
            *(ull*)(vo + 3*VSTR) = add2(add2(a3, core), b13);
            *(ull*)(vo + 4*VSTR) = add2(add2(a4, core), b14);
            *(ull*)(vo + 5*VSTR) = add2(add2(a5, core), b15);
            *(ull*)(vo + 6*VSTR) = add2(add2(a6, core), b16);
            *(ull*)(vo + 7*VSTR) = add2(core, b17);
        }
        __syncthreads();

        // ======== combined phase: P1(pair p+1) overlapped with P2b(pair p) ====
        if (p + 1 < 85) {
            float* nxtT = sTmpB + (((p + 1) & 1) ? 2*BPLANE : 0);
            phase1x2(2*(p+1), nxtT, nxtT + BPLANE);
        }

        #pragma unroll
        for (int half = 0; half < 2; half++) {
            if (half == 1 && !has1) break;
            const float* sTmp = curT + half*BPLANE;
            const float* sV   = sVB  + half*SVPLANE;

            const float* rowp = sV + yo*VSTR + xs;
            float4 q0 = *(const float4*)rowp;
            float4 q1 = *(const float4*)(rowp + 4);
            float4 q2 = *(const float4*)(rowp + 8);
            float2 q3 = *(const float2*)(rowp + 12);
            float v0 = q0.x, v1 = q0.y, v2  = q0.z, v3  = q0.w;
            float v4 = q1.x, v5 = q1.y, v6  = q1.z, v7  = q1.w;
            float v8 = q2.x, v9 = q2.y, v10 = q2.z, v11 = q2.w;
            float v12 = q3.x, v13 = q3.y;

            float core = __fadd_rn(
                __fadd_rn(__fadd_rn(v3, v4), __fadd_rn(v5, v6)),
                __fadd_rn(__fadd_rn(v7, v8), __fadd_rn(v9, v10)));
            float a2 = v2;
            float a1 = __fadd_rn(v1, a2);
            float a0 = __fadd_rn(v0, a1);
            float c11 = v11;
            float c12 = __fadd_rn(c11, v12);
            float c13 = __fadd_rn(c12, v13);

            float s0 = __fadd_rn(a0, core);
            float s1 = __fadd_rn(__fadd_rn(a1, core), c11);
            float s2 = __fadd_rn(__fadd_rn(a2, core), c12);
            float s3 = __fadd_rn(core, c13);

            const int cb = (yo + RAD)*TMPSTR + (xs + RAD);
            float t0 = sTmp[cb + 0];
            float t1 = sTmp[cb + 1];
            float t2 = sTmp[cb + 2];
            float t3 = sTmp[cb + 3];

            // argmin over s (== argmin over w = s/121); ties -> newer candidate
            if (s0 <= wm0) { wm0 = s0; r0 = t0; }
            if (s1 <= wm1) { wm1 = s1; r1 = t1; }
            if (s2 <= wm2) { wm2 = s2; r2 = t2; }
            if (s3 <= wm3) { wm3 = s3; r3 = t3; }
        }
        __syncthreads();   // orders P2b reads & next P1 writes before P2a(p+1)
    }

    float4 out4 = make_float4(r0, r1, r2, r3);
    *(float4*)(g_res + (by0 + yo)*W + (bx0 + xs)) = out4;
}

// ---- final 3x3 min-pool (inf pad == clamped window) ----
__global__ void minpool3(float* __restrict__ out) {
    int x = blockIdx.x*blockDim.x + threadIdx.x;
    int y = blockIdx.y*blockDim.y + threadIdx.y;
    if (x >= W || y >= H) return;
    float m = CUDART_INF_F;
    #pragma unroll
    for (int dy = -1; dy <= 1; dy++) {
        int yy = y + dy;
        if ((unsigned)yy >= (unsigned)H) continue;
        const float* row = g_res + yy*W;
        #pragma unroll
        for (int dx = -1; dx <= 1; dx++) {
            int xx = x + dx;
            if ((unsigned)xx < (unsigned)W) m = fminf(m, row[xx]);
        }
    }
    out[y*W + x] = m;
}

extern "C" void kernel_launch(void* const* d_in, const int* in_sizes, int n_in,
                              void* d_out, int out_size) {
    const float* A = (const float*)d_in[0];
    const float* B = (const float*)d_in[1];
    float* out = (float*)d_out;

    cudaFuncSetAttribute(dewarp_main,
                         cudaFuncAttributeMaxDynamicSharedMemorySize, SMEM_BYTES);

    dim3 grid(W/TS, H/TS);
    dewarp_main<<<grid, NTH, SMEM_BYTES>>>(A, B);

    dim3 b2(32, 8);
    dim3 g2(W/32, H/8);
    minpool3<<<g2, b2>>>(out);
}